// round 1
// baseline (speedup 1.0000x reference)
#include <cuda_runtime.h>
#include <cstdint>

// ---------------------------------------------------------------------------
// D_MPNNLayer: fused MPNN layer on GB300
//   xab = x @ [A|B]^T  (node GEMM, A=W1[:,0:128], B=W1[:,128:256])
//   per edge: m = relu(h@C^T + xa[dst] + xb[src]); red.v4 -> m_node[dst]
//   p = m_node @ W2^T  (node GEMM)
//   out[e] = relu(LN(p[src[e]] * snorm_n[e]))
// ---------------------------------------------------------------------------

constexpr int NN = 40000;        // nodes
constexpr int NE = 640000;       // edges
constexpr int LDA = 132;         // padded smem row stride (floats) for K=128
constexpr int SMEM_FLOATS = 128 * LDA + 64 * LDA;          // BsT + As
constexpr int SMEM_BYTES = SMEM_FLOATS * 4 + 128 * 4;      // + sdst/ssrc

__device__ float g_xab[(size_t)NN * 256];    // [node][0:128)=xa(dst part), [128:256)=xb(src part)
__device__ float g_mnode[(size_t)NN * 128];  // segment sum
__device__ float g_p[(size_t)NN * 128];      // m_node @ W2^T

// ---------------- packed fp32x2 helpers (FFMA2 path on sm_103a) ------------
__device__ __forceinline__ unsigned long long fma2(unsigned long long a,
                                                   unsigned long long b,
                                                   unsigned long long c) {
    unsigned long long d;
    asm("fma.rn.f32x2 %0, %1, %2, %3;" : "=l"(d) : "l"(a), "l"(b), "l"(c));
    return d;
}
__device__ __forceinline__ unsigned long long pk2(float v) {
    unsigned long long d;
    unsigned int u = __float_as_uint(v);
    asm("mov.b64 %0, {%1, %1};" : "=l"(d) : "r"(u));
    return d;
}
__device__ __forceinline__ float2 upk2(unsigned long long v) {
    unsigned int lo, hi;
    asm("mov.b64 {%0, %1}, %2;" : "=r"(lo), "=r"(hi) : "l"(v));
    return make_float2(__uint_as_float(lo), __uint_as_float(hi));
}
__device__ __forceinline__ float4 mk4(float2 a, float2 b) {
    return make_float4(a.x, a.y, b.x, b.y);
}

// ---------------- staging helpers ------------------------------------------
// Stage 128x128 weight block B[jj][k] = wbase[jj*wstride + k] into BsT[k][jj]
// (k-major). Mapping jj-fast across the warp -> conflict-free smem stores.
__device__ __forceinline__ void stage_B(float* BsT, const float* __restrict__ wbase,
                                        int wstride) {
    for (int idx = threadIdx.x; idx < 4096; idx += 256) {
        int jj = idx & 127, k4 = idx >> 7;
        float4 v = *(const float4*)(wbase + (size_t)jj * wstride + k4 * 4);
        BsT[(k4 * 4 + 0) * LDA + jj] = v.x;
        BsT[(k4 * 4 + 1) * LDA + jj] = v.y;
        BsT[(k4 * 4 + 2) * LDA + jj] = v.z;
        BsT[(k4 * 4 + 3) * LDA + jj] = v.w;
    }
}
// Stage 64x128 activation tile row-major (coalesced, conflict-free)
__device__ __forceinline__ void stage_A(float* As, const float* __restrict__ arow0) {
    for (int idx = threadIdx.x; idx < 2048; idx += 256) {
        int r = idx >> 5, k4 = idx & 31;
        *(float4*)(As + r * LDA + k4 * 4) = *(const float4*)(arow0 + (size_t)r * 128 + k4 * 4);
    }
}

// ---------------- 64x128 tile GEMM core (K=128), fp32x2 packed FMA ---------
// 256 threads as (ty 0..15, tx 0..15): thread -> rows ty*4..+3, cols tx*8..+7
__device__ __forceinline__ void tile_mma(const float* __restrict__ As,
                                         const float* __restrict__ BsT,
                                         int tx, int ty,
                                         unsigned long long acc[4][4]) {
    const float* ar = As + ty * 4 * LDA;
#pragma unroll 4
    for (int k = 0; k < 128; k++) {
        unsigned long long ap0 = pk2(ar[k]);
        unsigned long long ap1 = pk2(ar[k + 1 * LDA]);
        unsigned long long ap2 = pk2(ar[k + 2 * LDA]);
        unsigned long long ap3 = pk2(ar[k + 3 * LDA]);
        const ulonglong2* bp = (const ulonglong2*)(BsT + k * LDA + tx * 8);
        ulonglong2 b01 = bp[0];
        ulonglong2 b23 = bp[1];
        acc[0][0] = fma2(ap0, b01.x, acc[0][0]);
        acc[0][1] = fma2(ap0, b01.y, acc[0][1]);
        acc[0][2] = fma2(ap0, b23.x, acc[0][2]);
        acc[0][3] = fma2(ap0, b23.y, acc[0][3]);
        acc[1][0] = fma2(ap1, b01.x, acc[1][0]);
        acc[1][1] = fma2(ap1, b01.y, acc[1][1]);
        acc[1][2] = fma2(ap1, b23.x, acc[1][2]);
        acc[1][3] = fma2(ap1, b23.y, acc[1][3]);
        acc[2][0] = fma2(ap2, b01.x, acc[2][0]);
        acc[2][1] = fma2(ap2, b01.y, acc[2][1]);
        acc[2][2] = fma2(ap2, b23.x, acc[2][2]);
        acc[2][3] = fma2(ap2, b23.y, acc[2][3]);
        acc[3][0] = fma2(ap3, b01.x, acc[3][0]);
        acc[3][1] = fma2(ap3, b01.y, acc[3][1]);
        acc[3][2] = fma2(ap3, b23.x, acc[3][2]);
        acc[3][3] = fma2(ap3, b23.y, acc[3][3]);
    }
}

// ---------------- kernels ---------------------------------------------------
__global__ void k_zero() {
    int i = blockIdx.x * blockDim.x + threadIdx.x;  // 5000*256 = 1.28M float4 exactly
    ((float4*)g_mnode)[i] = make_float4(0.f, 0.f, 0.f, 0.f);
}

// xab[n, half*128 + j] = sum_k x[n,k] * W1[j, half*128 + k]
__global__ void __launch_bounds__(256, 2) k_xab(const float* __restrict__ x,
                                                const float* __restrict__ W1) {
    extern __shared__ float smem[];
    float* BsT = smem;
    float* As = smem + 128 * LDA;
    int half = blockIdx.y;
    stage_B(BsT, W1 + half * 128, 384);
    int m0 = blockIdx.x * 64;
    stage_A(As, x + (size_t)m0 * 128);
    __syncthreads();

    int tx = threadIdx.x & 15, ty = threadIdx.x >> 4;
    unsigned long long acc[4][4] = {};
    tile_mma(As, BsT, tx, ty, acc);

#pragma unroll
    for (int i = 0; i < 4; i++) {
        int row = m0 + ty * 4 + i;
        float* op = g_xab + (size_t)row * 256 + half * 128 + tx * 8;
        *(float4*)op = mk4(upk2(acc[i][0]), upk2(acc[i][1]));
        *(float4*)(op + 4) = mk4(upk2(acc[i][2]), upk2(acc[i][3]));
    }
}

// per edge tile: acc = h @ C^T ; m = relu(acc + xa[dst] + xb[src]) ; red -> m_node[dst]
__global__ void __launch_bounds__(256, 2) k_edge(const float* __restrict__ h,
                                                 const float* __restrict__ W1,
                                                 const int* __restrict__ src,
                                                 const int* __restrict__ dst) {
    extern __shared__ float smem[];
    float* BsT = smem;
    float* As = smem + 128 * LDA;
    int* sdst = (int*)(smem + SMEM_FLOATS);
    int* ssrc = sdst + 64;

    stage_B(BsT, W1 + 256, 384);  // C block of W1
    int tx = threadIdx.x & 15, ty = threadIdx.x >> 4;

    for (int tile = blockIdx.x; tile < NE / 64; tile += gridDim.x) {
        int e0 = tile * 64;
        stage_A(As, h + (size_t)e0 * 128);
        if (threadIdx.x < 64) {
            sdst[threadIdx.x] = dst[e0 + threadIdx.x];
            ssrc[threadIdx.x] = src[e0 + threadIdx.x];
        }
        __syncthreads();

        unsigned long long acc[4][4] = {};
        tile_mma(As, BsT, tx, ty, acc);

#pragma unroll
        for (int i = 0; i < 4; i++) {
            int de = sdst[ty * 4 + i];
            int se = ssrc[ty * 4 + i];
            const float* xap = g_xab + (size_t)de * 256 + tx * 8;
            const float* xbp = g_xab + (size_t)se * 256 + 128 + tx * 8;
            float4 xa0 = *(const float4*)xap;
            float4 xa1 = *(const float4*)(xap + 4);
            float4 xb0 = *(const float4*)xbp;
            float4 xb1 = *(const float4*)(xbp + 4);
            float2 c0 = upk2(acc[i][0]), c1 = upk2(acc[i][1]);
            float2 c2 = upk2(acc[i][2]), c3 = upk2(acc[i][3]);
            float4 r0, r1;
            r0.x = fmaxf(c0.x + xa0.x + xb0.x, 0.f);
            r0.y = fmaxf(c0.y + xa0.y + xb0.y, 0.f);
            r0.z = fmaxf(c1.x + xa0.z + xb0.z, 0.f);
            r0.w = fmaxf(c1.y + xa0.w + xb0.w, 0.f);
            r1.x = fmaxf(c2.x + xa1.x + xb1.x, 0.f);
            r1.y = fmaxf(c2.y + xa1.y + xb1.y, 0.f);
            r1.z = fmaxf(c3.x + xa1.z + xb1.z, 0.f);
            r1.w = fmaxf(c3.y + xa1.w + xb1.w, 0.f);
            float* mp = g_mnode + (size_t)de * 128 + tx * 8;
            asm volatile("red.global.add.v4.f32 [%0], {%1,%2,%3,%4};" ::"l"(mp),
                         "f"(r0.x), "f"(r0.y), "f"(r0.z), "f"(r0.w)
                         : "memory");
            asm volatile("red.global.add.v4.f32 [%0], {%1,%2,%3,%4};" ::"l"(mp + 4),
                         "f"(r1.x), "f"(r1.y), "f"(r1.z), "f"(r1.w)
                         : "memory");
        }
        __syncthreads();
    }
}

// p = m_node @ W2^T
__global__ void __launch_bounds__(256, 2) k_p(const float* __restrict__ W2) {
    extern __shared__ float smem[];
    float* BsT = smem;
    float* As = smem + 128 * LDA;
    stage_B(BsT, W2, 128);
    int m0 = blockIdx.x * 64;
    stage_A(As, g_mnode + (size_t)m0 * 128);
    __syncthreads();

    int tx = threadIdx.x & 15, ty = threadIdx.x >> 4;
    unsigned long long acc[4][4] = {};
    tile_mma(As, BsT, tx, ty, acc);

#pragma unroll
    for (int i = 0; i < 4; i++) {
        int row = m0 + ty * 4 + i;
        float* op = g_p + (size_t)row * 128 + tx * 8;
        *(float4*)op = mk4(upk2(acc[i][0]), upk2(acc[i][1]));
        *(float4*)(op + 4) = mk4(upk2(acc[i][2]), upk2(acc[i][3]));
    }
}

// out[e] = relu(LN(p[src[e]] * snorm_n[e]) * gamma + beta), warp per edge row
__global__ void __launch_bounds__(256) k_ln(const float* __restrict__ snorm,
                                            const int* __restrict__ src,
                                            const float* __restrict__ gamma,
                                            const float* __restrict__ beta,
                                            float* __restrict__ out) {
    int w = threadIdx.x >> 5, lane = threadIdx.x & 31;
    int e = blockIdx.x * 8 + w;
    float s = snorm[e];
    int sp = src[e];
    float4 v = ((const float4*)(g_p + (size_t)sp * 128))[lane];
    v.x *= s; v.y *= s; v.z *= s; v.w *= s;
    float sum = v.x + v.y + v.z + v.w;
    float ssq = v.x * v.x + v.y * v.y + v.z * v.z + v.w * v.w;
#pragma unroll
    for (int o = 16; o > 0; o >>= 1) {
        sum += __shfl_xor_sync(0xffffffffu, sum, o);
        ssq += __shfl_xor_sync(0xffffffffu, ssq, o);
    }
    float mean = sum * 0.0078125f;
    float var = ssq * 0.0078125f - mean * mean;
    float rstd = rsqrtf(var + 1e-5f);
    float4 g = ((const float4*)gamma)[lane];
    float4 b = ((const float4*)beta)[lane];
    float4 o4;
    o4.x = fmaxf((v.x - mean) * rstd * g.x + b.x, 0.f);
    o4.y = fmaxf((v.y - mean) * rstd * g.y + b.y, 0.f);
    o4.z = fmaxf((v.z - mean) * rstd * g.z + b.z, 0.f);
    o4.w = fmaxf((v.w - mean) * rstd * g.w + b.w, 0.f);
    ((float4*)(out + (size_t)e * 128))[lane] = o4;
}

// ---------------------------------------------------------------------------
extern "C" void kernel_launch(void* const* d_in, const int* in_sizes, int n_in,
                              void* d_out, int out_size) {
    const float* x = (const float*)d_in[0];
    const float* h = (const float*)d_in[1];
    const float* snorm_n = (const float*)d_in[2];
    // d_in[3] = snorm_e (unused by reference forward)
    const float* W1 = (const float*)d_in[4];
    const float* W2 = (const float*)d_in[5];
    const float* gamma = (const float*)d_in[6];
    const float* beta = (const float*)d_in[7];
    const int* src = (const int*)d_in[8];
    const int* dst = (const int*)d_in[9];
    float* out = (float*)d_out;

    cudaFuncSetAttribute(k_xab, cudaFuncAttributeMaxDynamicSharedMemorySize, SMEM_BYTES);
    cudaFuncSetAttribute(k_edge, cudaFuncAttributeMaxDynamicSharedMemorySize, SMEM_BYTES);
    cudaFuncSetAttribute(k_p, cudaFuncAttributeMaxDynamicSharedMemorySize, SMEM_BYTES);

    k_zero<<<5000, 256>>>();
    k_xab<<<dim3(NN / 64, 2), 256, SMEM_BYTES>>>(x, W1);
    k_edge<<<296, 256, SMEM_BYTES>>>(h, W1, src, dst);
    k_p<<<NN / 64, 256, SMEM_BYTES>>>(W2);
    k_ln<<<NE / 8, 256>>>(snorm_n, src, gamma, beta, out);
}

// round 3
// speedup vs baseline: 1.3890x; 1.3890x over previous
#include <cuda_runtime.h>
#include <cstdint>

// ---------------------------------------------------------------------------
// D_MPNNLayer on GB300 (sm_103a, compiled via compute_103 -> mma.sync path)
//   k_xab_mma: xab = x @ [A|B]^T           (tf32 mma.sync)
//   k_edge_mma: m = relu(h@C^T + xa[dst] + xb[src]); red.v2 -> m_node[dst]
//   k_p: p = m_node @ W2^T                 (FFMA2, exact fp32)
//   k_ln: out[e] = relu(LN(p[src[e]] * snorm_n[e]))
// ---------------------------------------------------------------------------

constexpr int NN = 40000;
constexpr int NE = 640000;

// tf32 mma tiles: 128x128, smem row stride 132 words (conflict-free fragments)
constexpr int LDT = 132;
constexpr int TILE_WORDS = 128 * LDT;                 // 16896 words = 67584 B
constexpr int SMEM_EDGE = (3 * TILE_WORDS) * 4 + 2048;  // B + A0 + A1 + idx
constexpr int SMEM_XAB = (2 * TILE_WORDS) * 4;          // B + A

// FFMA2 path (k_p)
constexpr int LDA = 132;
constexpr int SMEM_BYTES_F = (128 * LDA + 64 * LDA) * 4 + 128 * 4;

__device__ float g_xab[(size_t)NN * 256];
__device__ float g_mnode[(size_t)NN * 128];
__device__ float g_p[(size_t)NN * 128];

// ---------------- helpers ----------------------------------------------------
__device__ __forceinline__ uint32_t cvt_tf32(float f) {
    uint32_t r;
    asm("cvt.rna.tf32.f32 %0, %1;" : "=r"(r) : "f"(f));
    return r;
}
__device__ __forceinline__ void mma8(float acc[4], uint32_t a0, uint32_t a1, uint32_t a2,
                                     uint32_t a3, uint32_t b0, uint32_t b1) {
    asm("mma.sync.aligned.m16n8k8.row.col.f32.tf32.tf32.f32 "
        "{%0,%1,%2,%3}, {%4,%5,%6,%7}, {%8,%9}, {%0,%1,%2,%3};"
        : "+f"(acc[0]), "+f"(acc[1]), "+f"(acc[2]), "+f"(acc[3])
        : "r"(a0), "r"(a1), "r"(a2), "r"(a3), "r"(b0), "r"(b1));
}

// Stage a 128-row x 128-col fp32 block -> tf32, row-major, stride LDT.
__device__ __forceinline__ void stage128_tf32(uint32_t* S, const float* __restrict__ g,
                                              int gstride, int nrows) {
#pragma unroll
    for (int i = 0; i < 16; i++) {
        int idx = threadIdx.x + i * 256;
        int r = idx >> 5, k4 = idx & 31;
        float4 v = make_float4(0.f, 0.f, 0.f, 0.f);
        if (r < nrows) v = *(const float4*)(g + (size_t)r * gstride + k4 * 4);
        uint4 w;
        w.x = cvt_tf32(v.x); w.y = cvt_tf32(v.y);
        w.z = cvt_tf32(v.z); w.w = cvt_tf32(v.w);
        *(uint4*)(S + r * LDT + k4 * 4) = w;
    }
}

// Warp-tile mma core: warp (wm,wn) computes rows wm*32..+31, cols wn*64..+63
__device__ __forceinline__ void mma_tile_core(const uint32_t* __restrict__ As,
                                              const uint32_t* __restrict__ Bs, int lane,
                                              int wm, int wn, float acc[2][8][4]) {
    const uint32_t* ab = As + (wm * 32 + (lane >> 2)) * LDT + (lane & 3);
    const uint32_t* bb = Bs + (wn * 64 + (lane >> 2)) * LDT + (lane & 3);
#pragma unroll
    for (int ks = 0; ks < 16; ks++) {
        int k0 = ks * 8;
        uint32_t b[8][2];
#pragma unroll
        for (int nt = 0; nt < 8; nt++) {
            b[nt][0] = bb[nt * 8 * LDT + k0];
            b[nt][1] = bb[nt * 8 * LDT + k0 + 4];
        }
#pragma unroll
        for (int mt = 0; mt < 2; mt++) {
            uint32_t a0 = ab[(mt * 16 + 0) * LDT + k0];
            uint32_t a1 = ab[(mt * 16 + 8) * LDT + k0];
            uint32_t a2 = ab[(mt * 16 + 0) * LDT + k0 + 4];
            uint32_t a3 = ab[(mt * 16 + 8) * LDT + k0 + 4];
#pragma unroll
            for (int nt = 0; nt < 8; nt++) mma8(acc[mt][nt], a0, a1, a2, a3, b[nt][0], b[nt][1]);
        }
    }
}

// ---------------- FFMA2 helpers (k_p) ----------------------------------------
__device__ __forceinline__ unsigned long long fma2(unsigned long long a, unsigned long long b,
                                                   unsigned long long c) {
    unsigned long long d;
    asm("fma.rn.f32x2 %0, %1, %2, %3;" : "=l"(d) : "l"(a), "l"(b), "l"(c));
    return d;
}
__device__ __forceinline__ unsigned long long pk2(float v) {
    unsigned long long d;
    unsigned int u = __float_as_uint(v);
    asm("mov.b64 %0, {%1, %1};" : "=l"(d) : "r"(u));
    return d;
}
__device__ __forceinline__ float2 upk2(unsigned long long v) {
    unsigned int lo, hi;
    asm("mov.b64 {%0, %1}, %2;" : "=r"(lo), "=r"(hi) : "l"(v));
    return make_float2(__uint_as_float(lo), __uint_as_float(hi));
}
__device__ __forceinline__ float4 mk4(float2 a, float2 b) {
    return make_float4(a.x, a.y, b.x, b.y);
}
__device__ __forceinline__ void stage_B_f(float* BsT, const float* __restrict__ wbase,
                                          int wstride) {
    for (int idx = threadIdx.x; idx < 4096; idx += 256) {
        int jj = idx & 127, k4 = idx >> 7;
        float4 v = *(const float4*)(wbase + (size_t)jj * wstride + k4 * 4);
        BsT[(k4 * 4 + 0) * LDA + jj] = v.x;
        BsT[(k4 * 4 + 1) * LDA + jj] = v.y;
        BsT[(k4 * 4 + 2) * LDA + jj] = v.z;
        BsT[(k4 * 4 + 3) * LDA + jj] = v.w;
    }
}
__device__ __forceinline__ void stage_A_f(float* As, const float* __restrict__ arow0) {
    for (int idx = threadIdx.x; idx < 2048; idx += 256) {
        int r = idx >> 5, k4 = idx & 31;
        *(float4*)(As + r * LDA + k4 * 4) = *(const float4*)(arow0 + (size_t)r * 128 + k4 * 4);
    }
}
__device__ __forceinline__ void tile_mma_f(const float* __restrict__ As,
                                           const float* __restrict__ BsT, int tx, int ty,
                                           unsigned long long acc[4][4]) {
    const float* ar = As + ty * 4 * LDA;
#pragma unroll 4
    for (int k = 0; k < 128; k++) {
        unsigned long long ap0 = pk2(ar[k]);
        unsigned long long ap1 = pk2(ar[k + 1 * LDA]);
        unsigned long long ap2 = pk2(ar[k + 2 * LDA]);
        unsigned long long ap3 = pk2(ar[k + 3 * LDA]);
        const ulonglong2* bp = (const ulonglong2*)(BsT + k * LDA + tx * 8);
        ulonglong2 b01 = bp[0];
        ulonglong2 b23 = bp[1];
        acc[0][0] = fma2(ap0, b01.x, acc[0][0]);
        acc[0][1] = fma2(ap0, b01.y, acc[0][1]);
        acc[0][2] = fma2(ap0, b23.x, acc[0][2]);
        acc[0][3] = fma2(ap0, b23.y, acc[0][3]);
        acc[1][0] = fma2(ap1, b01.x, acc[1][0]);
        acc[1][1] = fma2(ap1, b01.y, acc[1][1]);
        acc[1][2] = fma2(ap1, b23.x, acc[1][2]);
        acc[1][3] = fma2(ap1, b23.y, acc[1][3]);
        acc[2][0] = fma2(ap2, b01.x, acc[2][0]);
        acc[2][1] = fma2(ap2, b01.y, acc[2][1]);
        acc[2][2] = fma2(ap2, b23.x, acc[2][2]);
        acc[2][3] = fma2(ap2, b23.y, acc[2][3]);
        acc[3][0] = fma2(ap3, b01.x, acc[3][0]);
        acc[3][1] = fma2(ap3, b01.y, acc[3][1]);
        acc[3][2] = fma2(ap3, b23.x, acc[3][2]);
        acc[3][3] = fma2(ap3, b23.y, acc[3][3]);
    }
}

// ---------------- kernels ----------------------------------------------------
__global__ void k_zero() {
    int i = blockIdx.x * blockDim.x + threadIdx.x;
    ((float4*)g_mnode)[i] = make_float4(0.f, 0.f, 0.f, 0.f);
}

// xab via tf32 mma: per CTA 128 nodes x 128 outs (half selects W1 col block)
__global__ void __launch_bounds__(256, 1) k_xab_mma(const float* __restrict__ x,
                                                    const float* __restrict__ W1) {
    extern __shared__ uint32_t sm[];
    uint32_t* Bs = sm;
    uint32_t* As = sm + TILE_WORDS;
    int lane = threadIdx.x & 31, wid = threadIdx.x >> 5;
    int wm = wid & 3, wn = wid >> 2;
    int half = blockIdx.y;
    int m0 = blockIdx.x * 128;
    int nrows = NN - m0 < 128 ? NN - m0 : 128;

    stage128_tf32(Bs, W1 + half * 128, 384, 128);
    stage128_tf32(As, x + (size_t)m0 * 128, 128, nrows);
    __syncthreads();

    float acc[2][8][4] = {};
    mma_tile_core(As, Bs, lane, wm, wn, acc);

    int g = lane >> 2, tt = lane & 3;
#pragma unroll
    for (int mt = 0; mt < 2; mt++)
#pragma unroll
        for (int i = 0; i < 2; i++) {
            int r = m0 + wm * 32 + mt * 16 + g + i * 8;
            if (r < NN) {
                float* op = g_xab + (size_t)r * 256 + half * 128 + wn * 64 + tt * 2;
#pragma unroll
                for (int nt = 0; nt < 8; nt++) {
                    float2 st = make_float2(acc[mt][nt][2 * i], acc[mt][nt][2 * i + 1]);
                    *(float2*)(op + nt * 8) = st;
                }
            }
        }
}

// edge kernel: tf32 mma h@C^T + fused gather/relu/red, persistent, dbl-buffered
__global__ void __launch_bounds__(256, 1) k_edge_mma(const float* __restrict__ h,
                                                     const float* __restrict__ W1,
                                                     const int* __restrict__ src,
                                                     const int* __restrict__ dst) {
    extern __shared__ uint32_t sm[];
    uint32_t* Bs = sm;
    uint32_t* A[2] = {sm + TILE_WORDS, sm + 2 * TILE_WORDS};
    int* idx[2] = {(int*)(sm + 3 * TILE_WORDS), (int*)(sm + 3 * TILE_WORDS) + 256};

    int tid = threadIdx.x, lane = tid & 31, wid = tid >> 5;
    int wm = wid & 3, wn = wid >> 2;
    int g = lane >> 2, tt = lane & 3;

    stage128_tf32(Bs, W1 + 256, 384, 128);  // C block of W1

    const int G = gridDim.x;
    const int T = (5000 - blockIdx.x + G - 1) / G;

    // prologue: tile 0 -> buf 0
    {
        int e0 = blockIdx.x * 128;
        stage128_tf32(A[0], h + (size_t)e0 * 128, 128, 128);
        if (tid < 128) idx[0][tid] = dst[e0 + tid];
        else idx[0][tid] = src[e0 + tid - 128];
    }
    __syncthreads();

    for (int t = 0; t < T; t++) {
        int cur = t & 1;
        if (t + 1 < T) {
            int e0 = (blockIdx.x + (size_t)(t + 1) * G) * 128;
            stage128_tf32(A[1 - cur], h + (size_t)e0 * 128, 128, 128);
            if (tid < 128) idx[1 - cur][tid] = dst[e0 + tid];
            else idx[1 - cur][tid] = src[e0 + tid - 128];
        }

        float acc[2][8][4] = {};
        mma_tile_core(A[cur], Bs, lane, wm, wn, acc);

        const int* id = idx[cur];
#pragma unroll
        for (int mt = 0; mt < 2; mt++)
#pragma unroll
            for (int i = 0; i < 2; i++) {
                int r = wm * 32 + mt * 16 + g + i * 8;
                int de = id[r], se = id[128 + r];
                const float* xa = g_xab + (size_t)de * 256 + wn * 64 + tt * 2;
                const float* xb = g_xab + (size_t)se * 256 + 128 + wn * 64 + tt * 2;
                float* mp = g_mnode + (size_t)de * 128 + wn * 64 + tt * 2;
#pragma unroll
                for (int nt = 0; nt < 8; nt++) {
                    float2 va = *(const float2*)(xa + nt * 8);
                    float2 vb = *(const float2*)(xb + nt * 8);
                    float v0 = fmaxf(acc[mt][nt][2 * i] + va.x + vb.x, 0.f);
                    float v1 = fmaxf(acc[mt][nt][2 * i + 1] + va.y + vb.y, 0.f);
                    asm volatile("red.global.add.v2.f32 [%0], {%1,%2};" ::"l"(mp + nt * 8),
                                 "f"(v0), "f"(v1)
                                 : "memory");
                }
            }
        __syncthreads();
    }
}

// p = m_node @ W2^T (exact FFMA2)
__global__ void __launch_bounds__(256, 2) k_p(const float* __restrict__ W2) {
    extern __shared__ float smf[];
    float* BsT = smf;
    float* As = smf + 128 * LDA;
    stage_B_f(BsT, W2, 128);
    int m0 = blockIdx.x * 64;
    stage_A_f(As, g_mnode + (size_t)m0 * 128);
    __syncthreads();
    int tx = threadIdx.x & 15, ty = threadIdx.x >> 4;
    unsigned long long acc[4][4] = {};
    tile_mma_f(As, BsT, tx, ty, acc);
#pragma unroll
    for (int i = 0; i < 4; i++) {
        int row = m0 + ty * 4 + i;
        float* op = g_p + (size_t)row * 128 + tx * 8;
        *(float4*)op = mk4(upk2(acc[i][0]), upk2(acc[i][1]));
        *(float4*)(op + 4) = mk4(upk2(acc[i][2]), upk2(acc[i][3]));
    }
}

__global__ void __launch_bounds__(256) k_ln(const float* __restrict__ snorm,
                                            const int* __restrict__ src,
                                            const float* __restrict__ gamma,
                                            const float* __restrict__ beta,
                                            float* __restrict__ out) {
    int w = threadIdx.x >> 5, lane = threadIdx.x & 31;
    int e = blockIdx.x * 8 + w;
    float s = snorm[e];
    int sp = src[e];
    float4 v = ((const float4*)(g_p + (size_t)sp * 128))[lane];
    v.x *= s; v.y *= s; v.z *= s; v.w *= s;
    float sum = v.x + v.y + v.z + v.w;
    float ssq = v.x * v.x + v.y * v.y + v.z * v.z + v.w * v.w;
#pragma unroll
    for (int o = 16; o > 0; o >>= 1) {
        sum += __shfl_xor_sync(0xffffffffu, sum, o);
        ssq += __shfl_xor_sync(0xffffffffu, ssq, o);
    }
    float mean = sum * 0.0078125f;
    float var = ssq * 0.0078125f - mean * mean;
    float rstd = rsqrtf(var + 1e-5f);
    float4 gg = ((const float4*)gamma)[lane];
    float4 b = ((const float4*)beta)[lane];
    float4 o4;
    o4.x = fmaxf((v.x - mean) * rstd * gg.x + b.x, 0.f);
    o4.y = fmaxf((v.y - mean) * rstd * gg.y + b.y, 0.f);
    o4.z = fmaxf((v.z - mean) * rstd * gg.z + b.z, 0.f);
    o4.w = fmaxf((v.w - mean) * rstd * gg.w + b.w, 0.f);
    ((float4*)(out + (size_t)e * 128))[lane] = o4;
}

// ---------------------------------------------------------------------------
extern "C" void kernel_launch(void* const* d_in, const int* in_sizes, int n_in,
                              void* d_out, int out_size) {
    const float* x = (const float*)d_in[0];
    const float* h = (const float*)d_in[1];
    const float* snorm_n = (const float*)d_in[2];
    const float* W1 = (const float*)d_in[4];
    const float* W2 = (const float*)d_in[5];
    const float* gamma = (const float*)d_in[6];
    const float* beta = (const float*)d_in[7];
    const int* src = (const int*)d_in[8];
    const int* dst = (const int*)d_in[9];
    float* out = (float*)d_out;

    cudaFuncSetAttribute(k_xab_mma, cudaFuncAttributeMaxDynamicSharedMemorySize, SMEM_XAB);
    cudaFuncSetAttribute(k_edge_mma, cudaFuncAttributeMaxDynamicSharedMemorySize, SMEM_EDGE);
    cudaFuncSetAttribute(k_p, cudaFuncAttributeMaxDynamicSharedMemorySize, SMEM_BYTES_F);

    k_zero<<<5000, 256>>>();
    k_xab_mma<<<dim3(313, 2), 256, SMEM_XAB>>>(x, W1);
    k_edge_mma<<<148, 256, SMEM_EDGE>>>(h, W1, src, dst);
    k_p<<<625, 256, SMEM_BYTES_F>>>(W2);
    k_ln<<<NE / 8, 256>>>(snorm_n, src, gamma, beta, out);
}

// round 4
// speedup vs baseline: 1.8265x; 1.3150x over previous
#include <cuda_runtime.h>
#include <cstdint>

// ---------------------------------------------------------------------------
// D_MPNNLayer on GB300 (sm_103a via compute_103 -> mma.sync tf32)
//   k_xab_mma: xab = x @ [A|B]^T
//   k_edge:    m = relu(h@C^T + xa[dst] + xb[src]); red.v2 -> m_node[dst]
//              (cp.async pipelined, 512 thr, 16 warps 4x4)
//   k_p_mma:   p = m_node @ W2^T
//   k_ln:      out[e] = relu(LN(p[src[e]] * snorm_n[e]))
// ---------------------------------------------------------------------------

constexpr int NN = 40000;
constexpr int NE = 640000;

constexpr int LDT = 132;                       // smem word stride (conflict-free)
constexpr int TW = 128 * LDT;                  // tile words
constexpr int EDGE_SMEM = (3 * TW) * 4 + 2048; // B + A0 + A1 + idx0/1
constexpr int XAB_SMEM = (2 * TW) * 4;

__device__ float g_xab[(size_t)NN * 256];
__device__ float g_mnode[(size_t)NN * 128];
__device__ float g_p[(size_t)NN * 128];

// ---------------- helpers ----------------------------------------------------
__device__ __forceinline__ uint32_t smem_u32(const void* p) {
    uint32_t a;
    asm("{ .reg .u64 t; cvta.to.shared.u64 t, %1; cvt.u32.u64 %0, t; }" : "=r"(a) : "l"(p));
    return a;
}
__device__ __forceinline__ uint32_t cvt_tf32(float f) {
    uint32_t r;
    asm("cvt.rna.tf32.f32 %0, %1;" : "=r"(r) : "f"(f));
    return r;
}
__device__ __forceinline__ void cpa16(uint32_t s, const void* g) {
    asm volatile("cp.async.cg.shared.global [%0], [%1], 16;" ::"r"(s), "l"(g));
}
__device__ __forceinline__ void cpa_commit() {
    asm volatile("cp.async.commit_group;" ::: "memory");
}
__device__ __forceinline__ void mma8(float acc[4], uint32_t a0, uint32_t a1, uint32_t a2,
                                     uint32_t a3, uint32_t b0, uint32_t b1) {
    asm("mma.sync.aligned.m16n8k8.row.col.f32.tf32.tf32.f32 "
        "{%0,%1,%2,%3}, {%4,%5,%6,%7}, {%8,%9}, {%0,%1,%2,%3};"
        : "+f"(acc[0]), "+f"(acc[1]), "+f"(acc[2]), "+f"(acc[3])
        : "r"(a0), "r"(a1), "r"(a2), "r"(a3), "r"(b0), "r"(b1));
}

// Stage 128x128 fp32 -> tf32(rna) into smem, stride LDT. NT threads.
template <int NT>
__device__ __forceinline__ void stage128_tf32(uint32_t* S, const float* __restrict__ g,
                                              int gstride, int nrows) {
#pragma unroll
    for (int i = 0; i < 4096 / NT; i++) {
        int idx = threadIdx.x + i * NT;
        int r = idx >> 5, k4 = idx & 31;
        float4 v = make_float4(0.f, 0.f, 0.f, 0.f);
        if (r < nrows) v = *(const float4*)(g + (size_t)r * gstride + k4 * 4);
        uint4 w;
        w.x = cvt_tf32(v.x); w.y = cvt_tf32(v.y);
        w.z = cvt_tf32(v.z); w.w = cvt_tf32(v.w);
        *(uint4*)(S + r * LDT + k4 * 4) = w;
    }
}

// ---------------- k_zero ------------------------------------------------------
__global__ void k_zero() {
    int i = blockIdx.x * blockDim.x + threadIdx.x;
    ((float4*)g_mnode)[i] = make_float4(0.f, 0.f, 0.f, 0.f);
}

// ---------------- node GEMM core (256 thr, warps 4x2, 128x128 tile) ----------
__device__ __forceinline__ void mma_core_256(const uint32_t* __restrict__ As,
                                             const uint32_t* __restrict__ Bs, int lane,
                                             int wm, int wn, float acc[2][8][4]) {
    int g = lane >> 2, tt = lane & 3;
    const uint32_t* ab = As + (wm * 32 + g) * LDT + tt;
    const uint32_t* bb = Bs + (wn * 64 + g) * LDT + tt;
#pragma unroll
    for (int ks = 0; ks < 16; ks++) {
        int k0 = ks * 8;
        uint32_t b[8][2];
#pragma unroll
        for (int nt = 0; nt < 8; nt++) {
            b[nt][0] = bb[nt * 8 * LDT + k0];
            b[nt][1] = bb[nt * 8 * LDT + k0 + 4];
        }
#pragma unroll
        for (int mt = 0; mt < 2; mt++) {
            uint32_t a0 = ab[(mt * 16 + 0) * LDT + k0];
            uint32_t a1 = ab[(mt * 16 + 8) * LDT + k0];
            uint32_t a2 = ab[(mt * 16 + 0) * LDT + k0 + 4];
            uint32_t a3 = ab[(mt * 16 + 8) * LDT + k0 + 4];
#pragma unroll
            for (int nt = 0; nt < 8; nt++) mma8(acc[mt][nt], a0, a1, a2, a3, b[nt][0], b[nt][1]);
        }
    }
}

template <int OUTSTRIDE>
__device__ __forceinline__ void node_gemm(const float* __restrict__ Ain,
                                          const float* __restrict__ W, int wstride,
                                          float* __restrict__ outbase, int m0) {
    extern __shared__ uint32_t sm[];
    uint32_t* Bs = sm;
    uint32_t* As = sm + TW;
    int lane = threadIdx.x & 31, wid = threadIdx.x >> 5;
    int wm = wid & 3, wn = wid >> 2;
    int nrows = NN - m0 < 128 ? NN - m0 : 128;

    stage128_tf32<256>(Bs, W, wstride, 128);
    stage128_tf32<256>(As, Ain + (size_t)m0 * 128, 128, nrows);
    __syncthreads();

    float acc[2][8][4] = {};
    mma_core_256(As, Bs, lane, wm, wn, acc);

    int g = lane >> 2, tt = lane & 3;
#pragma unroll
    for (int mt = 0; mt < 2; mt++)
#pragma unroll
        for (int i = 0; i < 2; i++) {
            int r = m0 + wm * 32 + mt * 16 + g + i * 8;
            if (r < NN) {
                float* op = outbase + (size_t)r * OUTSTRIDE + wn * 64 + tt * 2;
#pragma unroll
                for (int nt = 0; nt < 8; nt++)
                    *(float2*)(op + nt * 8) =
                        make_float2(acc[mt][nt][2 * i], acc[mt][nt][2 * i + 1]);
            }
        }
}

__global__ void __launch_bounds__(256, 1) k_xab_mma(const float* __restrict__ x,
                                                    const float* __restrict__ W1) {
    int half = blockIdx.y;
    node_gemm<256>(x, W1 + half * 128, 384, g_xab + half * 128, blockIdx.x * 128);
}

__global__ void __launch_bounds__(256, 1) k_p_mma(const float* __restrict__ W2) {
    node_gemm<128>(g_mnode, W2, 128, g_p, blockIdx.x * 128);
}

// ---------------- edge kernel: cp.async pipeline, 512 thr, 16 warps 4x4 ------
__global__ void __launch_bounds__(512, 1) k_edge(const float* __restrict__ h,
                                                 const float* __restrict__ W1,
                                                 const int* __restrict__ src,
                                                 const int* __restrict__ dst) {
    extern __shared__ uint32_t sm[];
    uint32_t* Bs = sm;
    uint32_t* A[2] = {sm + TW, sm + 2 * TW};
    int* idxb[2] = {(int*)(sm + 3 * TW), (int*)(sm + 3 * TW) + 256};
    uint32_t sb = smem_u32(sm);
    const uint32_t A_OFF[2] = {sb + TW * 4, sb + 2 * TW * 4};
    const uint32_t IDX_OFF[2] = {sb + 3 * TW * 4, sb + 3 * TW * 4 + 1024};

    int tid = threadIdx.x, lane = tid & 31, wid = tid >> 5;
    int wm = wid & 3, wn = wid >> 2;
    int g = lane >> 2, tt = lane & 3;

    stage128_tf32<512>((uint32_t*)Bs, W1 + 256, 384, 128);  // C block (rounded once)

    const int G = gridDim.x;
    const int T = (5000 - blockIdx.x + G - 1) / G;

    // prologue: tile 0 -> buf 0 (group 0)
    {
        int e0 = blockIdx.x * 128;
#pragma unroll
        for (int i = 0; i < 8; i++) {
            int idx = tid + i * 512;
            int r = idx >> 5, k4 = idx & 31;
            cpa16(A_OFF[0] + (uint32_t)(r * LDT + k4 * 4) * 4,
                  h + (size_t)e0 * 128 + r * 128 + k4 * 4);
        }
        if (tid < 32) cpa16(IDX_OFF[0] + tid * 16, dst + e0 + tid * 4);
        else if (tid < 64) cpa16(IDX_OFF[0] + 512 + (tid - 32) * 16, src + e0 + (tid - 32) * 4);
        cpa_commit();
    }

    for (int t = 0; t < T; t++) {
        int cur = t & 1;
        if (t + 1 < T) {
            int e0 = (blockIdx.x + (size_t)(t + 1) * G) * 128;
#pragma unroll
            for (int i = 0; i < 8; i++) {
                int idx = tid + i * 512;
                int r = idx >> 5, k4 = idx & 31;
                cpa16(A_OFF[1 - cur] + (uint32_t)(r * LDT + k4 * 4) * 4,
                      h + (size_t)e0 * 128 + r * 128 + k4 * 4);
            }
            if (tid < 32) cpa16(IDX_OFF[1 - cur] + tid * 16, dst + e0 + tid * 4);
            else if (tid < 64)
                cpa16(IDX_OFF[1 - cur] + 512 + (tid - 32) * 16, src + e0 + (tid - 32) * 4);
            cpa_commit();
            asm volatile("cp.async.wait_group 1;" ::: "memory");
        } else {
            asm volatile("cp.async.wait_group 0;" ::: "memory");
        }
        __syncthreads();  // A[cur], idx[cur] visible

        // in-place rna rounding of A[cur]
        {
            uint32_t* Ac = A[cur];
#pragma unroll
            for (int i = 0; i < 8; i++) {
                int idx = tid + i * 512;
                int r = idx >> 5, k4 = idx & 31;
                uint4* p = (uint4*)(Ac + r * LDT + k4 * 4);
                uint4 w = *p;
                w.x = cvt_tf32(__uint_as_float(w.x));
                w.y = cvt_tf32(__uint_as_float(w.y));
                w.z = cvt_tf32(__uint_as_float(w.z));
                w.w = cvt_tf32(__uint_as_float(w.w));
                *p = w;
            }
        }
        __syncthreads();

        // mma: warp (wm,wn) -> rows wm*32..+31, cols wn*32..+31
        float acc[2][4][4] = {};
        {
            const uint32_t* ab = A[cur] + (wm * 32 + g) * LDT + tt;
            const uint32_t* bb = Bs + (wn * 32 + g) * LDT + tt;
#pragma unroll
            for (int ks = 0; ks < 16; ks++) {
                int k0 = ks * 8;
                uint32_t b[4][2];
#pragma unroll
                for (int nt = 0; nt < 4; nt++) {
                    b[nt][0] = bb[nt * 8 * LDT + k0];
                    b[nt][1] = bb[nt * 8 * LDT + k0 + 4];
                }
#pragma unroll
                for (int mt = 0; mt < 2; mt++) {
                    uint32_t a0 = ab[(mt * 16 + 0) * LDT + k0];
                    uint32_t a1 = ab[(mt * 16 + 8) * LDT + k0];
                    uint32_t a2 = ab[(mt * 16 + 0) * LDT + k0 + 4];
                    uint32_t a3 = ab[(mt * 16 + 8) * LDT + k0 + 4];
#pragma unroll
                    for (int nt = 0; nt < 4; nt++)
                        mma8(acc[mt][nt], a0, a1, a2, a3, b[nt][0], b[nt][1]);
                }
            }
        }

        // pull indices into registers so the epilogue is smem-free
        int de[2][2], se[2][2];
        const int* id = idxb[cur];
#pragma unroll
        for (int mt = 0; mt < 2; mt++)
#pragma unroll
            for (int i = 0; i < 2; i++) {
                int r = wm * 32 + mt * 16 + g + i * 8;
                de[mt][i] = id[r];
                se[mt][i] = id[128 + r];
            }
        __syncthreads();  // all warps done with A[cur]/idx[cur]

        // epilogue: gather + relu + red (overlaps next tile's cp.async)
#pragma unroll
        for (int mt = 0; mt < 2; mt++)
#pragma unroll
            for (int i = 0; i < 2; i++) {
                int col = wn * 32 + tt * 2;
                const float* xa = g_xab + (size_t)de[mt][i] * 256 + col;
                const float* xb = g_xab + (size_t)se[mt][i] * 256 + 128 + col;
                float* mp = g_mnode + (size_t)de[mt][i] * 128 + col;
#pragma unroll
                for (int nt = 0; nt < 4; nt++) {
                    float2 va = *(const float2*)(xa + nt * 8);
                    float2 vb = *(const float2*)(xb + nt * 8);
                    float v0 = fmaxf(acc[mt][nt][2 * i] + va.x + vb.x, 0.f);
                    float v1 = fmaxf(acc[mt][nt][2 * i + 1] + va.y + vb.y, 0.f);
                    asm volatile("red.global.add.v2.f32 [%0], {%1,%2};" ::"l"(mp + nt * 8),
                                 "f"(v0), "f"(v1)
                                 : "memory");
                }
            }
    }
}

// ---------------- k_ln --------------------------------------------------------
__global__ void __launch_bounds__(256) k_ln(const float* __restrict__ snorm,
                                            const int* __restrict__ src,
                                            const float* __restrict__ gamma,
                                            const float* __restrict__ beta,
                                            float* __restrict__ out) {
    int w = threadIdx.x >> 5, lane = threadIdx.x & 31;
    int e = blockIdx.x * 8 + w;
    float s = snorm[e];
    int sp = src[e];
    float4 v = ((const float4*)(g_p + (size_t)sp * 128))[lane];
    v.x *= s; v.y *= s; v.z *= s; v.w *= s;
    float sum = v.x + v.y + v.z + v.w;
    float ssq = v.x * v.x + v.y * v.y + v.z * v.z + v.w * v.w;
#pragma unroll
    for (int o = 16; o > 0; o >>= 1) {
        sum += __shfl_xor_sync(0xffffffffu, sum, o);
        ssq += __shfl_xor_sync(0xffffffffu, ssq, o);
    }
    float mean = sum * 0.0078125f;
    float var = ssq * 0.0078125f - mean * mean;
    float rstd = rsqrtf(var + 1e-5f);
    float4 gg = ((const float4*)gamma)[lane];
    float4 b = ((const float4*)beta)[lane];
    float4 o4;
    o4.x = fmaxf((v.x - mean) * rstd * gg.x + b.x, 0.f);
    o4.y = fmaxf((v.y - mean) * rstd * gg.y + b.y, 0.f);
    o4.z = fmaxf((v.z - mean) * rstd * gg.z + b.z, 0.f);
    o4.w = fmaxf((v.w - mean) * rstd * gg.w + b.w, 0.f);
    ((float4*)(out + (size_t)e * 128))[lane] = o4;
}

// ---------------------------------------------------------------------------
extern "C" void kernel_launch(void* const* d_in, const int* in_sizes, int n_in,
                              void* d_out, int out_size) {
    const float* x = (const float*)d_in[0];
    const float* h = (const float*)d_in[1];
    const float* snorm_n = (const float*)d_in[2];
    const float* W1 = (const float*)d_in[4];
    const float* W2 = (const float*)d_in[5];
    const float* gamma = (const float*)d_in[6];
    const float* beta = (const float*)d_in[7];
    const int* src = (const int*)d_in[8];
    const int* dst = (const int*)d_in[9];
    float* out = (float*)d_out;

    cudaFuncSetAttribute(k_xab_mma, cudaFuncAttributeMaxDynamicSharedMemorySize, XAB_SMEM);
    cudaFuncSetAttribute(k_p_mma, cudaFuncAttributeMaxDynamicSharedMemorySize, XAB_SMEM);
    cudaFuncSetAttribute(k_edge, cudaFuncAttributeMaxDynamicSharedMemorySize, EDGE_SMEM);

    k_zero<<<5000, 256>>>();
    k_xab_mma<<<dim3(313, 2), 256, XAB_SMEM>>>(x, W1);
    k_edge<<<148, 512, EDGE_SMEM>>>(h, W1, src, dst);
    k_p_mma<<<313, 256, XAB_SMEM>>>(W2);
    k_ln<<<NE / 8, 256>>>(snorm_n, src, gamma, beta, out);
}

// round 5
// speedup vs baseline: 2.0818x; 1.1398x over previous
#include <cuda_runtime.h>
#include <cstdint>

// ---------------------------------------------------------------------------
// D_MPNNLayer on GB300 (sm_103a via compute_103 -> mma.sync tf32)
// Feature permutation l(r): mma B-row r carries W1 feature l(r), so that each
// thread's fragment pair maps to 4 consecutive output columns -> float4/red.v4.
//   l(r): bits6:5,b0 keep; bit4=b4; bits3:2=b2b1(tt); bit1=b3(nt&1)
// ---------------------------------------------------------------------------

constexpr int NN = 40000;
constexpr int NE = 640000;

constexpr int LDT = 132;
constexpr int TW = 128 * LDT;
constexpr int EDGE_SMEM = (3 * TW) * 4 + 2048;
constexpr int XAB_SMEM = (2 * TW) * 4;

__device__ float g_xab[(size_t)NN * 256];
__device__ float g_mnode[(size_t)NN * 128];
__device__ float g_p[(size_t)NN * 128];

__device__ __host__ __forceinline__ int permL(int r) {
    return (r & 0x61) | ((r >> 2) & 0x02) | ((r & 0x06) << 1) | (r & 0x10);
}

// ---------------- helpers ----------------------------------------------------
__device__ __forceinline__ uint32_t smem_u32(const void* p) {
    uint32_t a;
    asm("{ .reg .u64 t; cvta.to.shared.u64 t, %1; cvt.u32.u64 %0, t; }" : "=r"(a) : "l"(p));
    return a;
}
__device__ __forceinline__ uint32_t cvt_tf32(float f) {
    uint32_t r;
    asm("cvt.rna.tf32.f32 %0, %1;" : "=r"(r) : "f"(f));
    return r;
}
__device__ __forceinline__ void cpa16(uint32_t s, const void* g) {
    asm volatile("cp.async.cg.shared.global [%0], [%1], 16;" ::"r"(s), "l"(g));
}
__device__ __forceinline__ void cpa_commit() {
    asm volatile("cp.async.commit_group;" ::: "memory");
}
__device__ __forceinline__ void mma8(float acc[4], uint32_t a0, uint32_t a1, uint32_t a2,
                                     uint32_t a3, uint32_t b0, uint32_t b1) {
    asm("mma.sync.aligned.m16n8k8.row.col.f32.tf32.tf32.f32 "
        "{%0,%1,%2,%3}, {%4,%5,%6,%7}, {%8,%9}, {%0,%1,%2,%3};"
        : "+f"(acc[0]), "+f"(acc[1]), "+f"(acc[2]), "+f"(acc[3])
        : "r"(a0), "r"(a1), "r"(a2), "r"(a3), "r"(b0), "r"(b1));
}

// Stage 128x128 fp32 -> tf32(rna), optional row permutation for weight (B) tiles.
template <int NT, bool PERM>
__device__ __forceinline__ void stage128_tf32(uint32_t* S, const float* __restrict__ g,
                                              int gstride, int nrows) {
#pragma unroll
    for (int i = 0; i < 4096 / NT; i++) {
        int idx = threadIdx.x + i * NT;
        int r = idx >> 5, k4 = idx & 31;
        int rl = PERM ? permL(r) : r;
        float4 v = make_float4(0.f, 0.f, 0.f, 0.f);
        if (rl < nrows) v = *(const float4*)(g + (size_t)rl * gstride + k4 * 4);
        uint4 w;
        w.x = cvt_tf32(v.x); w.y = cvt_tf32(v.y);
        w.z = cvt_tf32(v.z); w.w = cvt_tf32(v.w);
        *(uint4*)(S + r * LDT + k4 * 4) = w;
    }
}

__global__ void k_zero() {
    int i = blockIdx.x * blockDim.x + threadIdx.x;
    ((float4*)g_mnode)[i] = make_float4(0.f, 0.f, 0.f, 0.f);
}

// ---------------- node GEMM (256 thr, warps 4x2, 128x128 tile) ---------------
__device__ __forceinline__ void mma_core_256(const uint32_t* __restrict__ As,
                                             const uint32_t* __restrict__ Bs, int lane,
                                             int wm, int wn, float acc[2][8][4]) {
    int g = lane >> 2, tt = lane & 3;
    const uint32_t* ab = As + (wm * 32 + g) * LDT + tt;
    const uint32_t* bb = Bs + (wn * 64 + g) * LDT + tt;
#pragma unroll
    for (int ks = 0; ks < 16; ks++) {
        int k0 = ks * 8;
        uint32_t b[8][2];
#pragma unroll
        for (int nt = 0; nt < 8; nt++) {
            b[nt][0] = bb[nt * 8 * LDT + k0];
            b[nt][1] = bb[nt * 8 * LDT + k0 + 4];
        }
#pragma unroll
        for (int mt = 0; mt < 2; mt++) {
            uint32_t a0 = ab[(mt * 16 + 0) * LDT + k0];
            uint32_t a1 = ab[(mt * 16 + 8) * LDT + k0];
            uint32_t a2 = ab[(mt * 16 + 0) * LDT + k0 + 4];
            uint32_t a3 = ab[(mt * 16 + 8) * LDT + k0 + 4];
#pragma unroll
            for (int nt = 0; nt < 8; nt++) mma8(acc[mt][nt], a0, a1, a2, a3, b[nt][0], b[nt][1]);
        }
    }
}

// xab: B rows permuted, output column = l(row) -> g_xab identity feature order
__global__ void __launch_bounds__(256, 1) k_xab_mma(const float* __restrict__ x,
                                                    const float* __restrict__ W1) {
    extern __shared__ uint32_t sm[];
    uint32_t* Bs = sm;
    uint32_t* As = sm + TW;
    int lane = threadIdx.x & 31, wid = threadIdx.x >> 5;
    int wm = wid & 3, wn = wid >> 2;
    int half = blockIdx.y;
    int m0 = blockIdx.x * 128;
    int nrows = NN - m0 < 128 ? NN - m0 : 128;

    stage128_tf32<256, true>(Bs, W1 + half * 128, 384, 128);
    stage128_tf32<256, false>(As, x + (size_t)m0 * 128, 128, nrows);
    __syncthreads();

    float acc[2][8][4] = {};
    mma_core_256(As, Bs, lane, wm, wn, acc);

    int g = lane >> 2, tt = lane & 3;
#pragma unroll
    for (int mt = 0; mt < 2; mt++)
#pragma unroll
        for (int i = 0; i < 2; i++) {
            int r = m0 + wm * 32 + mt * 16 + g + i * 8;
            if (r < NN) {
                float* op = g_xab + (size_t)r * 256 + half * 128;
#pragma unroll
                for (int nt = 0; nt < 8; nt++) {
                    int col = permL(wn * 64 + nt * 8 + tt * 2);
                    *(float2*)(op + col) =
                        make_float2(acc[mt][nt][2 * i], acc[mt][nt][2 * i + 1]);
                }
            }
        }
}

// p = m_node @ W2^T (m_node is identity-ordered; no permutation needed)
__global__ void __launch_bounds__(256, 1) k_p_mma(const float* __restrict__ W2) {
    extern __shared__ uint32_t sm[];
    uint32_t* Bs = sm;
    uint32_t* As = sm + TW;
    int lane = threadIdx.x & 31, wid = threadIdx.x >> 5;
    int wm = wid & 3, wn = wid >> 2;
    int m0 = blockIdx.x * 128;
    int nrows = NN - m0 < 128 ? NN - m0 : 128;

    stage128_tf32<256, false>(Bs, W2, 128, 128);
    stage128_tf32<256, false>(As, g_mnode + (size_t)m0 * 128, 128, nrows);
    __syncthreads();

    float acc[2][8][4] = {};
    mma_core_256(As, Bs, lane, wm, wn, acc);

    int g = lane >> 2, tt = lane & 3;
#pragma unroll
    for (int mt = 0; mt < 2; mt++)
#pragma unroll
        for (int i = 0; i < 2; i++) {
            int r = m0 + wm * 32 + mt * 16 + g + i * 8;
            if (r < NN) {
                float* op = g_p + (size_t)r * 128 + wn * 64 + tt * 2;
#pragma unroll
                for (int nt = 0; nt < 8; nt++)
                    *(float2*)(op + nt * 8) =
                        make_float2(acc[mt][nt][2 * i], acc[mt][nt][2 * i + 1]);
            }
        }
}

// ---------------- edge kernel: cp.async pipeline + permuted B + v4 epilogue --
__global__ void __launch_bounds__(512, 1) k_edge(const float* __restrict__ h,
                                                 const float* __restrict__ W1,
                                                 const int* __restrict__ src,
                                                 const int* __restrict__ dst) {
    extern __shared__ uint32_t sm[];
    uint32_t* Bs = sm;
    uint32_t* A[2] = {sm + TW, sm + 2 * TW};
    int* idxb[2] = {(int*)(sm + 3 * TW), (int*)(sm + 3 * TW) + 256};
    uint32_t sb = smem_u32(sm);
    const uint32_t A_OFF[2] = {sb + TW * 4, sb + 2 * TW * 4};
    const uint32_t IDX_OFF[2] = {sb + 3 * TW * 4, sb + 3 * TW * 4 + 1024};

    int tid = threadIdx.x, lane = tid & 31, wid = tid >> 5;
    int wm = wid & 3, wn = wid >> 2;
    int g = lane >> 2, tt = lane & 3;

    stage128_tf32<512, true>(Bs, W1 + 256, 384, 128);  // C block, rows permuted

    const int G = gridDim.x;
    const int T = (5000 - blockIdx.x + G - 1) / G;

    {
        int e0 = blockIdx.x * 128;
#pragma unroll
        for (int i = 0; i < 8; i++) {
            int idx = tid + i * 512;
            int r = idx >> 5, k4 = idx & 31;
            cpa16(A_OFF[0] + (uint32_t)(r * LDT + k4 * 4) * 4,
                  h + (size_t)e0 * 128 + r * 128 + k4 * 4);
        }
        if (tid < 32) cpa16(IDX_OFF[0] + tid * 16, dst + e0 + tid * 4);
        else if (tid < 64) cpa16(IDX_OFF[0] + 512 + (tid - 32) * 16, src + e0 + (tid - 32) * 4);
        cpa_commit();
    }

    for (int t = 0; t < T; t++) {
        int cur = t & 1;
        if (t + 1 < T) {
            int e0 = (blockIdx.x + (size_t)(t + 1) * G) * 128;
#pragma unroll
            for (int i = 0; i < 8; i++) {
                int idx = tid + i * 512;
                int r = idx >> 5, k4 = idx & 31;
                cpa16(A_OFF[1 - cur] + (uint32_t)(r * LDT + k4 * 4) * 4,
                      h + (size_t)e0 * 128 + r * 128 + k4 * 4);
            }
            if (tid < 32) cpa16(IDX_OFF[1 - cur] + tid * 16, dst + e0 + tid * 4);
            else if (tid < 64)
                cpa16(IDX_OFF[1 - cur] + 512 + (tid - 32) * 16, src + e0 + (tid - 32) * 4);
            cpa_commit();
            asm volatile("cp.async.wait_group 1;" ::: "memory");
        } else {
            asm volatile("cp.async.wait_group 0;" ::: "memory");
        }
        __syncthreads();

        // in-place rna rounding of A[cur]
        {
            uint32_t* Ac = A[cur];
#pragma unroll
            for (int i = 0; i < 8; i++) {
                int idx = tid + i * 512;
                int r = idx >> 5, k4 = idx & 31;
                uint4* p = (uint4*)(Ac + r * LDT + k4 * 4);
                uint4 w = *p;
                w.x = cvt_tf32(__uint_as_float(w.x));
                w.y = cvt_tf32(__uint_as_float(w.y));
                w.z = cvt_tf32(__uint_as_float(w.z));
                w.w = cvt_tf32(__uint_as_float(w.w));
                *p = w;
            }
        }
        __syncthreads();

        float acc[2][4][4] = {};
        {
            const uint32_t* ab = A[cur] + (wm * 32 + g) * LDT + tt;
            const uint32_t* bb = Bs + (wn * 32 + g) * LDT + tt;
#pragma unroll
            for (int ks = 0; ks < 16; ks++) {
                int k0 = ks * 8;
                uint32_t b[4][2];
#pragma unroll
                for (int nt = 0; nt < 4; nt++) {
                    b[nt][0] = bb[nt * 8 * LDT + k0];
                    b[nt][1] = bb[nt * 8 * LDT + k0 + 4];
                }
#pragma unroll
                for (int mt = 0; mt < 2; mt++) {
                    uint32_t a0 = ab[(mt * 16 + 0) * LDT + k0];
                    uint32_t a1 = ab[(mt * 16 + 8) * LDT + k0];
                    uint32_t a2 = ab[(mt * 16 + 0) * LDT + k0 + 4];
                    uint32_t a3 = ab[(mt * 16 + 8) * LDT + k0 + 4];
#pragma unroll
                    for (int nt = 0; nt < 4; nt++)
                        mma8(acc[mt][nt], a0, a1, a2, a3, b[nt][0], b[nt][1]);
                }
            }
        }

        int de[2][2], se[2][2];
        const int* id = idxb[cur];
#pragma unroll
        for (int mt = 0; mt < 2; mt++)
#pragma unroll
            for (int i = 0; i < 2; i++) {
                int r = wm * 32 + mt * 16 + g + i * 8;
                de[mt][i] = id[r];
                se[mt][i] = id[128 + r];
            }
        __syncthreads();

        // epilogue: fragment pair (2P, 2P+1) -> 4 consecutive cols at
        // wn*32 + P*16 + tt*4 (by construction of permL). float4 + red.v4.
#pragma unroll
        for (int mt = 0; mt < 2; mt++)
#pragma unroll
            for (int i = 0; i < 2; i++) {
                const float* xaB = g_xab + (size_t)de[mt][i] * 256;
                const float* xbB = g_xab + (size_t)se[mt][i] * 256 + 128;
                float* mpB = g_mnode + (size_t)de[mt][i] * 128;
#pragma unroll
                for (int P = 0; P < 2; P++) {
                    int col = wn * 32 + P * 16 + tt * 4;
                    float4 va = *(const float4*)(xaB + col);
                    float4 vb = *(const float4*)(xbB + col);
                    float v0 = fmaxf(acc[mt][2 * P][2 * i] + va.x + vb.x, 0.f);
                    float v1 = fmaxf(acc[mt][2 * P][2 * i + 1] + va.y + vb.y, 0.f);
                    float v2 = fmaxf(acc[mt][2 * P + 1][2 * i] + va.z + vb.z, 0.f);
                    float v3 = fmaxf(acc[mt][2 * P + 1][2 * i + 1] + va.w + vb.w, 0.f);
                    asm volatile("red.global.add.v4.f32 [%0], {%1,%2,%3,%4};" ::"l"(mpB + col),
                                 "f"(v0), "f"(v1), "f"(v2), "f"(v3)
                                 : "memory");
                }
            }
    }
}

// ---------------- k_ln --------------------------------------------------------
__global__ void __launch_bounds__(256) k_ln(const float* __restrict__ snorm,
                                            const int* __restrict__ src,
                                            const float* __restrict__ gamma,
                                            const float* __restrict__ beta,
                                            float* __restrict__ out) {
    int w = threadIdx.x >> 5, lane = threadIdx.x & 31;
    int e = blockIdx.x * 8 + w;
    float s = snorm[e];
    int sp = src[e];
    float4 v = ((const float4*)(g_p + (size_t)sp * 128))[lane];
    v.x *= s; v.y *= s; v.z *= s; v.w *= s;
    float sum = v.x + v.y + v.z + v.w;
    float ssq = v.x * v.x + v.y * v.y + v.z * v.z + v.w * v.w;
#pragma unroll
    for (int o = 16; o > 0; o >>= 1) {
        sum += __shfl_xor_sync(0xffffffffu, sum, o);
        ssq += __shfl_xor_sync(0xffffffffu, ssq, o);
    }
    float mean = sum * 0.0078125f;
    float var = ssq * 0.0078125f - mean * mean;
    float rstd = rsqrtf(var + 1e-5f);
    float4 gg = ((const float4*)gamma)[lane];
    float4 b = ((const float4*)beta)[lane];
    float4 o4;
    o4.x = fmaxf((v.x - mean) * rstd * gg.x + b.x, 0.f);
    o4.y = fmaxf((v.y - mean) * rstd * gg.y + b.y, 0.f);
    o4.z = fmaxf((v.z - mean) * rstd * gg.z + b.z, 0.f);
    o4.w = fmaxf((v.w - mean) * rstd * gg.w + b.w, 0.f);
    ((float4*)(out + (size_t)e * 128))[lane] = o4;
}

// ---------------------------------------------------------------------------
extern "C" void kernel_launch(void* const* d_in, const int* in_sizes, int n_in,
                              void* d_out, int out_size) {
    const float* x = (const float*)d_in[0];
    const float* h = (const float*)d_in[1];
    const float* snorm_n = (const float*)d_in[2];
    const float* W1 = (const float*)d_in[4];
    const float* W2 = (const float*)d_in[5];
    const float* gamma = (const float*)d_in[6];
    const float* beta = (const float*)d_in[7];
    const int* src = (const int*)d_in[8];
    const int* dst = (const int*)d_in[9];
    float* out = (float*)d_out;

    cudaFuncSetAttribute(k_xab_mma, cudaFuncAttributeMaxDynamicSharedMemorySize, XAB_SMEM);
    cudaFuncSetAttribute(k_p_mma, cudaFuncAttributeMaxDynamicSharedMemorySize, XAB_SMEM);
    cudaFuncSetAttribute(k_edge, cudaFuncAttributeMaxDynamicSharedMemorySize, EDGE_SMEM);

    k_zero<<<5000, 256>>>();
    k_xab_mma<<<dim3(313, 2), 256, XAB_SMEM>>>(x, W1);
    k_edge<<<148, 512, EDGE_SMEM>>>(h, W1, src, dst);
    k_p_mma<<<313, 256, XAB_SMEM>>>(W2);
    k_ln<<<NE / 8, 256>>>(snorm_n, src, gamma, beta, out);
}